// round 3
// baseline (speedup 1.0000x reference)
#include <cuda_runtime.h>
#include <cstdint>
#include <math.h>

// Problem constants (bi_Mlp: x[64,197,768], H=3072)
#define MTOK 12608
#define CDIM 768
#define HDIM 3072

#define BM 128
#define BN 128
#define BK 32
#define NSTAGE 3
#define TSTRIDE 36                 // padded row stride (floats) -> conflict-free frags
#define TILE_WORDS (128 * TSTRIDE) // one tile (A or B) per stage

// Scratch (static device globals: allocation-guard safe)
__device__ float g_h[(size_t)MTOK * HDIM];
__device__ float g_w1s[(size_t)HDIM * CDIM];
__device__ float g_w2s[(size_t)CDIM * HDIM];
__device__ float g_alpha1[HDIM];
__device__ float g_alpha2[CDIM];

// ---------------------------------------------------------------------------
// helpers
// ---------------------------------------------------------------------------
__device__ __forceinline__ uint32_t smem_u32(const void* p) {
    return (uint32_t)__cvta_generic_to_shared(p);
}

__device__ __forceinline__ void cp_async16(uint32_t dst, const void* src, int src_bytes) {
    asm volatile("cp.async.cg.shared.global [%0], [%1], 16, %2;\n"
                 :: "r"(dst), "l"(src), "r"(src_bytes));
}
__device__ __forceinline__ void cp_commit() {
    asm volatile("cp.async.commit_group;\n" ::: "memory");
}
template <int N>
__device__ __forceinline__ void cp_wait() {
    asm volatile("cp.async.wait_group %0;\n" :: "n"(N) : "memory");
}

__device__ __forceinline__ uint32_t f2tf32(float f) {
    uint32_t r;
    asm("cvt.rna.tf32.f32 %0, %1;\n" : "=r"(r) : "f"(f));
    return r;
}

__device__ __forceinline__ void mma_tf32(float c[4], const uint32_t a[4], const uint32_t b[2]) {
    asm volatile(
        "mma.sync.aligned.m16n8k8.row.col.f32.tf32.tf32.f32 "
        "{%0,%1,%2,%3}, {%4,%5,%6,%7}, {%8,%9}, {%0,%1,%2,%3};\n"
        : "+f"(c[0]), "+f"(c[1]), "+f"(c[2]), "+f"(c[3])
        : "r"(a[0]), "r"(a[1]), "r"(a[2]), "r"(a[3]), "r"(b[0]), "r"(b[1]));
}

// ---------------------------------------------------------------------------
// binarize: per-row alpha = mean(|w|), ws = sign(w) in {-1,0,+1}
// ---------------------------------------------------------------------------
__global__ void binarize_kernel(const float* __restrict__ w, float* __restrict__ ws,
                                float* __restrict__ alpha, int cols) {
    int r = blockIdx.x;
    const float* wr = w + (size_t)r * cols;
    float* wsr = ws + (size_t)r * cols;
    float s = 0.f;
    for (int c = threadIdx.x; c < cols; c += blockDim.x) {
        float v = wr[c];
        s += fabsf(v);
        wsr[c] = (v > 0.f) ? 1.f : ((v < 0.f) ? -1.f : 0.f);
    }
    #pragma unroll
    for (int o = 16; o; o >>= 1) s += __shfl_xor_sync(0xffffffffu, s, o);
    __shared__ float red[8];
    if ((threadIdx.x & 31) == 0) red[threadIdx.x >> 5] = s;
    __syncthreads();
    if (threadIdx.x < 8) {
        float v = red[threadIdx.x];
        #pragma unroll
        for (int o = 4; o; o >>= 1) v += __shfl_xor_sync(0xffu, v, o);
        if (threadIdx.x == 0) alpha[r] = v / (float)cols;
    }
}

// ---------------------------------------------------------------------------
// GEMM: C[m,n] = epi( alpha[n] * sum_k A[m,k]*B[n,k] + bias[n] )
// A: [M,K] row-major fp32 (tf32-rounded if CVT_A==false)
// B: [N,K] row-major, values in {-1,0,+1}
// EPI 0: gelu(exact)+clip, store tf32-rounded (feeds GEMM2)
// EPI 1: plain affine, store fp32
// ---------------------------------------------------------------------------
template <bool CVT_A, int EPI>
__global__ void __launch_bounds__(256, 1)
gemm_bin(const float* __restrict__ A, const float* __restrict__ B,
         const float* __restrict__ alpha, const float* __restrict__ bias,
         float* __restrict__ C, int M, int N, int K) {
    extern __shared__ float smem[];
    float* As = smem;
    float* Bs = smem + (size_t)NSTAGE * TILE_WORDS;

    const int tid = threadIdx.x;
    const int lane = tid & 31;
    const int warp = tid >> 5;
    const int wm = warp & 3;   // 4 warps along M (4*32 = 128)
    const int wn = warp >> 2;  // 2 warps along N (2*64 = 128)
    const int m0 = blockIdx.y * BM;
    const int n0 = blockIdx.x * BN;
    const int g = lane >> 2, t = lane & 3;

    float acc[2][8][4];
    #pragma unroll
    for (int i = 0; i < 2; ++i)
        #pragma unroll
        for (int j = 0; j < 8; ++j)
            #pragma unroll
            for (int q = 0; q < 4; ++q) acc[i][j][q] = 0.f;

    const int Ktiles = K / BK;

    auto load_tile = [&](int kt, int s) {
        const int kbase = kt * BK;
        float* as = As + (size_t)s * TILE_WORDS;
        float* bs = Bs + (size_t)s * TILE_WORDS;
        #pragma unroll
        for (int p = 0; p < 4; ++p) {
            int idx = p * 256 + tid;     // 0..1023
            int row = idx >> 3;          // 0..127
            int seg = idx & 7;           // 0..7 (16B each)
            // A (guard M)
            int am = m0 + row;
            bool pa = am < M;
            const float* gpa = A + (size_t)(pa ? am : 0) * K + kbase + seg * 4;
            cp_async16(smem_u32(as + row * TSTRIDE + seg * 4), gpa, pa ? 16 : 0);
            // B (always in-bounds: N,K are tile multiples)
            const float* gpb = B + (size_t)(n0 + row) * K + kbase + seg * 4;
            cp_async16(smem_u32(bs + row * TSTRIDE + seg * 4), gpb, 16);
        }
    };

    // prologue: stages 0..NSTAGE-2
    #pragma unroll
    for (int s = 0; s < NSTAGE - 1; ++s) {
        load_tile(s, s);
        cp_commit();
    }

    for (int kt = 0; kt < Ktiles; ++kt) {
        cp_wait<NSTAGE - 2>();
        __syncthreads();

        int knext = kt + NSTAGE - 1;
        if (knext < Ktiles) load_tile(knext, knext % NSTAGE);
        cp_commit();

        const float* as = As + (size_t)(kt % NSTAGE) * TILE_WORDS;
        const float* bs = Bs + (size_t)(kt % NSTAGE) * TILE_WORDS;

        #pragma unroll
        for (int kk = 0; kk < 4; ++kk) {
            const int c0 = kk * 8 + t;
            uint32_t af[2][4];
            #pragma unroll
            for (int mi = 0; mi < 2; ++mi) {
                int r = wm * 32 + mi * 16 + g;
                float a0 = as[r * TSTRIDE + c0];
                float a1 = as[(r + 8) * TSTRIDE + c0];
                float a2 = as[r * TSTRIDE + c0 + 4];
                float a3 = as[(r + 8) * TSTRIDE + c0 + 4];
                if (CVT_A) {
                    af[mi][0] = f2tf32(a0); af[mi][1] = f2tf32(a1);
                    af[mi][2] = f2tf32(a2); af[mi][3] = f2tf32(a3);
                } else {
                    af[mi][0] = __float_as_uint(a0); af[mi][1] = __float_as_uint(a1);
                    af[mi][2] = __float_as_uint(a2); af[mi][3] = __float_as_uint(a3);
                }
            }
            uint32_t bf[8][2];
            #pragma unroll
            for (int ni = 0; ni < 8; ++ni) {
                int n = wn * 64 + ni * 8 + g;
                bf[ni][0] = __float_as_uint(bs[n * TSTRIDE + c0]);
                bf[ni][1] = __float_as_uint(bs[n * TSTRIDE + c0 + 4]);
            }
            #pragma unroll
            for (int mi = 0; mi < 2; ++mi)
                #pragma unroll
                for (int ni = 0; ni < 8; ++ni)
                    mma_tf32(acc[mi][ni], af[mi], bf[ni]);
        }
    }

    // epilogue
    #pragma unroll
    for (int ni = 0; ni < 8; ++ni) {
        int col = n0 + wn * 64 + ni * 8 + t * 2;
        float al0 = alpha[col], al1 = alpha[col + 1];
        float bi0 = bias[col], bi1 = bias[col + 1];
        #pragma unroll
        for (int mi = 0; mi < 2; ++mi) {
            int row = m0 + wm * 32 + mi * 16 + g;
            #pragma unroll
            for (int h = 0; h < 2; ++h) { // h=0: rows g, h=1: rows g+8
                int r = row + h * 8;
                if (r < M) {
                    float v0 = al0 * acc[mi][ni][h * 2 + 0] + bi0;
                    float v1 = al1 * acc[mi][ni][h * 2 + 1] + bi1;
                    if (EPI == 0) {
                        v0 = 0.5f * v0 * (1.f + erff(v0 * 0.7071067811865476f));
                        v1 = 0.5f * v1 * (1.f + erff(v1 * 0.7071067811865476f));
                        v0 = fminf(fmaxf(v0, -10.f), 10.f);
                        v1 = fminf(fmaxf(v1, -10.f), 10.f);
                        // pre-round to tf32 so GEMM2 skips conversion
                        C[(size_t)r * N + col]     = __uint_as_float(f2tf32(v0));
                        C[(size_t)r * N + col + 1] = __uint_as_float(f2tf32(v1));
                    } else {
                        C[(size_t)r * N + col]     = v0;
                        C[(size_t)r * N + col + 1] = v1;
                    }
                }
            }
        }
    }
}

// ---------------------------------------------------------------------------
extern "C" void kernel_launch(void* const* d_in, const int* in_sizes, int n_in,
                              void* d_out, int out_size) {
    const float* x  = (const float*)d_in[0];
    const float* w1 = (const float*)d_in[1];
    const float* b1 = (const float*)d_in[2];
    const float* w2 = (const float*)d_in[3];
    const float* b2 = (const float*)d_in[4];
    float* out = (float*)d_out;

    const int M = in_sizes[0] / CDIM;   // 12608
    const int H = in_sizes[2];          // 3072
    const int C = in_sizes[4];          // 768

    float *hbuf, *w1s, *w2s, *a1, *a2;
    cudaGetSymbolAddress((void**)&hbuf, g_h);
    cudaGetSymbolAddress((void**)&w1s, g_w1s);
    cudaGetSymbolAddress((void**)&w2s, g_w2s);
    cudaGetSymbolAddress((void**)&a1, g_alpha1);
    cudaGetSymbolAddress((void**)&a2, g_alpha2);

    binarize_kernel<<<H, 256>>>(w1, w1s, a1, C);
    binarize_kernel<<<C, 256>>>(w2, w2s, a2, H);

    size_t smem = (size_t)NSTAGE * 2 * TILE_WORDS * sizeof(float); // 110,592 B
    cudaFuncSetAttribute((const void*)gemm_bin<true, 0>,
                         cudaFuncAttributeMaxDynamicSharedMemorySize, (int)smem);
    cudaFuncSetAttribute((const void*)gemm_bin<false, 1>,
                         cudaFuncAttributeMaxDynamicSharedMemorySize, (int)smem);

    dim3 grid1(H / BN, (M + BM - 1) / BM);
    gemm_bin<true, 0><<<grid1, 256, smem>>>(x, w1s, a1, b1, hbuf, M, H, C);

    dim3 grid2(C / BN, (M + BM - 1) / BM);
    gemm_bin<false, 1><<<grid2, 256, smem>>>(hbuf, w2s, a2, b2, out, M, C, H);
}

// round 6
// speedup vs baseline: 1.8499x; 1.8499x over previous
#include <cuda_runtime.h>
#include <cuda_fp16.h>
#include <cstdint>
#include <math.h>

// Problem constants (bi_Mlp: x[64,197,768], H=3072)
#define MTOK 12608
#define CDIM 768
#define HDIM 3072

#define BM 128
#define BN 128
#define BK 32               // halves of K per tile
#define NSTAGE 4
#define RSTRIDE_H 40        // halves per smem row (32 data + 8 pad) -> conflict-free
#define RSTRIDE_W 20        // 32-bit words per row
#define TILE_BYTES (128 * RSTRIDE_H * 2)      // 10240
#define STAGE_BYTES (2 * TILE_BYTES)          // 20480 (A + B)
#define SMEM_TOTAL (NSTAGE * STAGE_BYTES)     // 81920

// Scratch (static device globals: allocation-guard safe)
__device__ __half g_xh[(size_t)MTOK * CDIM];   // x in fp16
__device__ __half g_h [(size_t)MTOK * HDIM];   // hidden (fp16, post-GELU)
__device__ __half g_w1h[(size_t)HDIM * CDIM];  // sign(w1) in fp16
__device__ __half g_w2h[(size_t)CDIM * HDIM];  // sign(w2) in fp16
__device__ float  g_alpha1[HDIM];
__device__ float  g_alpha2[CDIM];

// ---------------------------------------------------------------------------
// helpers
// ---------------------------------------------------------------------------
__device__ __forceinline__ uint32_t smem_u32(const void* p) {
    return (uint32_t)__cvta_generic_to_shared(p);
}
__device__ __forceinline__ void cp_async16(uint32_t dst, const void* src, int src_bytes) {
    asm volatile("cp.async.cg.shared.global [%0], [%1], 16, %2;\n"
                 :: "r"(dst), "l"(src), "r"(src_bytes));
}
__device__ __forceinline__ void cp_commit() {
    asm volatile("cp.async.commit_group;\n" ::: "memory");
}
template <int N>
__device__ __forceinline__ void cp_wait() {
    asm volatile("cp.async.wait_group %0;\n" :: "n"(N) : "memory");
}
// fp16 MMA, fp32 accumulate: D[16,8] += A[16,16] * B[16,8]
__device__ __forceinline__ void mma_f16(float c[4], const uint32_t a[4], const uint32_t b[2]) {
    asm volatile(
        "mma.sync.aligned.m16n8k16.row.col.f32.f16.f16.f32 "
        "{%0,%1,%2,%3}, {%4,%5,%6,%7}, {%8,%9}, {%0,%1,%2,%3};\n"
        : "+f"(c[0]), "+f"(c[1]), "+f"(c[2]), "+f"(c[3])
        : "r"(a[0]), "r"(a[1]), "r"(a[2]), "r"(a[3]), "r"(b[0]), "r"(b[1]));
}

// ---------------------------------------------------------------------------
// prep kernels
// ---------------------------------------------------------------------------
__global__ void convert_x_kernel(const float* __restrict__ x, __half* __restrict__ xh, int n4) {
    int i = blockIdx.x * blockDim.x + threadIdx.x;
    if (i < n4) {
        float4 v = ((const float4*)x)[i];
        __half2 h0 = __floats2half2_rn(v.x, v.y);
        __half2 h1 = __floats2half2_rn(v.z, v.w);
        uint2 u;
        u.x = *(uint32_t*)&h0;
        u.y = *(uint32_t*)&h1;
        ((uint2*)xh)[i] = u;
    }
}

__global__ void binarize_h_kernel(const float* __restrict__ w, __half* __restrict__ ws,
                                  float* __restrict__ alpha, int cols) {
    int r = blockIdx.x;
    const float* wr = w + (size_t)r * cols;
    __half* wsr = ws + (size_t)r * cols;
    float s = 0.f;
    for (int c = threadIdx.x; c < cols; c += blockDim.x) {
        float v = wr[c];
        s += fabsf(v);
        wsr[c] = __float2half((v > 0.f) ? 1.f : ((v < 0.f) ? -1.f : 0.f));
    }
    #pragma unroll
    for (int o = 16; o; o >>= 1) s += __shfl_xor_sync(0xffffffffu, s, o);
    __shared__ float red[8];
    if ((threadIdx.x & 31) == 0) red[threadIdx.x >> 5] = s;
    __syncthreads();
    if (threadIdx.x < 8) {
        float v = red[threadIdx.x];
        #pragma unroll
        for (int o = 4; o; o >>= 1) v += __shfl_xor_sync(0xffu, v, o);
        if (threadIdx.x == 0) alpha[r] = v / (float)cols;
    }
}

// ---------------------------------------------------------------------------
// GEMM: C[m,n] = epi( alpha[n] * sum_k A[m,k]*B[n,k] + bias[n] )
// A: [M,K] row-major fp16, B: [N,K] row-major fp16 (values ±1)
// EPI 0: gelu(exact)+clip, store fp16 (feeds GEMM2); EPI 1: affine, store fp32
// ---------------------------------------------------------------------------
template <int EPI>
__global__ void __launch_bounds__(256, 2)
gemm_bin(const __half* __restrict__ A, const __half* __restrict__ B,
         const float* __restrict__ alpha, const float* __restrict__ bias,
         void* __restrict__ outp, int M, int N, int K) {
    extern __shared__ __align__(128) char smem[];

    const int tid = threadIdx.x;
    const int lane = tid & 31;
    const int warp = tid >> 5;
    const int wm = warp & 3;   // 4 warps along M (4*32 = 128)
    const int wn = warp >> 2;  // 2 warps along N (2*64 = 128)
    const int m0 = blockIdx.y * BM;
    const int n0 = blockIdx.x * BN;
    const int g = lane >> 2, t = lane & 3;

    float acc[2][8][4];
    #pragma unroll
    for (int i = 0; i < 2; ++i)
        #pragma unroll
        for (int j = 0; j < 8; ++j)
            #pragma unroll
            for (int q = 0; q < 4; ++q) acc[i][j][q] = 0.f;

    const int Ktiles = K / BK;

    auto load_tile = [&](int kt, int s) {
        const size_t kb = (size_t)kt * BK;     // halves
        char* as = smem + (size_t)s * STAGE_BYTES;
        char* bs = as + TILE_BYTES;
        #pragma unroll
        for (int p = 0; p < 2; ++p) {
            int idx = p * 256 + tid;     // 0..511
            int row = idx >> 2;          // 0..127
            int seg = idx & 3;           // 0..3 (16B each; row = 64B data)
            // A (guard M)
            int am = m0 + row;
            bool pa = am < M;
            const __half* gpa = A + (size_t)(pa ? am : 0) * K + kb + seg * 8;
            cp_async16(smem_u32(as + row * (RSTRIDE_H * 2) + seg * 16), gpa, pa ? 16 : 0);
            // B (always in-bounds: N,K are tile multiples)
            const __half* gpb = B + (size_t)(n0 + row) * K + kb + seg * 8;
            cp_async16(smem_u32(bs + row * (RSTRIDE_H * 2) + seg * 16), gpb, 16);
        }
    };

    // prologue
    #pragma unroll
    for (int s = 0; s < NSTAGE - 1; ++s) {
        load_tile(s, s);
        cp_commit();
    }

    for (int kt = 0; kt < Ktiles; ++kt) {
        cp_wait<NSTAGE - 2>();
        __syncthreads();

        int knext = kt + NSTAGE - 1;
        if (knext < Ktiles) load_tile(knext, knext % NSTAGE);
        cp_commit();

        const uint32_t* as32 = (const uint32_t*)(smem + (size_t)(kt % NSTAGE) * STAGE_BYTES);
        const uint32_t* bs32 = (const uint32_t*)(smem + (size_t)(kt % NSTAGE) * STAGE_BYTES + TILE_BYTES);

        #pragma unroll
        for (int kk = 0; kk < 2; ++kk) {          // two K=16 chunks per BK=32
            const int w0 = kk * 8 + t;            // word index within row
            uint32_t af[2][4];
            #pragma unroll
            for (int mi = 0; mi < 2; ++mi) {
                int r = wm * 32 + mi * 16 + g;
                af[mi][0] = as32[r * RSTRIDE_W + w0];            // A[g][2t..2t+1]
                af[mi][1] = as32[(r + 8) * RSTRIDE_W + w0];      // A[g+8][..]
                af[mi][2] = as32[r * RSTRIDE_W + w0 + 4];        // A[g][2t+8..]
                af[mi][3] = as32[(r + 8) * RSTRIDE_W + w0 + 4];
            }
            uint32_t bf[8][2];
            #pragma unroll
            for (int ni = 0; ni < 8; ++ni) {
                int n = wn * 64 + ni * 8 + g;
                bf[ni][0] = bs32[n * RSTRIDE_W + w0];
                bf[ni][1] = bs32[n * RSTRIDE_W + w0 + 4];
            }
            #pragma unroll
            for (int mi = 0; mi < 2; ++mi)
                #pragma unroll
                for (int ni = 0; ni < 8; ++ni)
                    mma_f16(acc[mi][ni], af[mi], bf[ni]);
        }
    }

    // epilogue (accumulator layout identical to validated tf32 version)
    #pragma unroll
    for (int ni = 0; ni < 8; ++ni) {
        int col = n0 + wn * 64 + ni * 8 + t * 2;
        float al0 = alpha[col], al1 = alpha[col + 1];
        float bi0 = bias[col], bi1 = bias[col + 1];
        #pragma unroll
        for (int mi = 0; mi < 2; ++mi) {
            int row = m0 + wm * 32 + mi * 16 + g;
            #pragma unroll
            for (int h = 0; h < 2; ++h) { // h=0: rows g, h=1: rows g+8
                int r = row + h * 8;
                if (r < M) {
                    float v0 = al0 * acc[mi][ni][h * 2 + 0] + bi0;
                    float v1 = al1 * acc[mi][ni][h * 2 + 1] + bi1;
                    if (EPI == 0) {
                        v0 = 0.5f * v0 * (1.f + erff(v0 * 0.7071067811865476f));
                        v1 = 0.5f * v1 * (1.f + erff(v1 * 0.7071067811865476f));
                        v0 = fminf(fmaxf(v0, -10.f), 10.f);
                        v1 = fminf(fmaxf(v1, -10.f), 10.f);
                        __half2 hv = __floats2half2_rn(v0, v1);
                        *(__half2*)((__half*)outp + (size_t)r * N + col) = hv;
                    } else {
                        float2 fv = make_float2(v0, v1);
                        *(float2*)((float*)outp + (size_t)r * N + col) = fv;
                    }
                }
            }
        }
    }
}

// ---------------------------------------------------------------------------
extern "C" void kernel_launch(void* const* d_in, const int* in_sizes, int n_in,
                              void* d_out, int out_size) {
    const float* x  = (const float*)d_in[0];
    const float* w1 = (const float*)d_in[1];
    const float* b1 = (const float*)d_in[2];
    const float* w2 = (const float*)d_in[3];
    const float* b2 = (const float*)d_in[4];

    const int M = in_sizes[0] / CDIM;   // 12608
    const int H = in_sizes[2];          // 3072
    const int C = in_sizes[4];          // 768

    __half *xh, *hbuf, *w1h, *w2h;
    float *a1, *a2;
    cudaGetSymbolAddress((void**)&xh,   g_xh);
    cudaGetSymbolAddress((void**)&hbuf, g_h);
    cudaGetSymbolAddress((void**)&w1h,  g_w1h);
    cudaGetSymbolAddress((void**)&w2h,  g_w2h);
    cudaGetSymbolAddress((void**)&a1,   g_alpha1);
    cudaGetSymbolAddress((void**)&a2,   g_alpha2);

    int n4 = (M * C) / 4;
    convert_x_kernel<<<(n4 + 255) / 256, 256>>>(x, xh, n4);
    binarize_h_kernel<<<H, 256>>>(w1, w1h, a1, C);
    binarize_h_kernel<<<C, 256>>>(w2, w2h, a2, H);

    cudaFuncSetAttribute((const void*)gemm_bin<0>,
                         cudaFuncAttributeMaxDynamicSharedMemorySize, SMEM_TOTAL);
    cudaFuncSetAttribute((const void*)gemm_bin<1>,
                         cudaFuncAttributeMaxDynamicSharedMemorySize, SMEM_TOTAL);

    dim3 grid1(H / BN, (M + BM - 1) / BM);   // (24, 99)
    gemm_bin<0><<<grid1, 256, SMEM_TOTAL>>>(xh, w1h, a1, b1, hbuf, M, H, C);

    dim3 grid2(C / BN, (M + BM - 1) / BM);   // (6, 99)
    gemm_bin<1><<<grid2, 256, SMEM_TOTAL>>>(hbuf, w2h, a2, b2, d_out, M, C, H);
}

// round 7
// speedup vs baseline: 2.0935x; 1.1317x over previous
#include <cuda_runtime.h>
#include <cuda_fp16.h>
#include <cstdint>
#include <math.h>

// Problem constants (bi_Mlp: x[64,197,768], H=3072)
#define MTOK 12608
#define CDIM 768
#define HDIM 3072

#define BM 128
#define BN 128
#define BK 32               // halves of K per tile
#define NSTAGE 4
#define RSTRIDE_H 40        // halves per smem row (32 data + 8 pad) -> conflict-free
#define RSTRIDE_B 80        // bytes per smem row
#define TILE_BYTES (128 * RSTRIDE_B)          // 10240
#define STAGE_BYTES (2 * TILE_BYTES)          // 20480 (A + B)
#define SMEM_TOTAL (NSTAGE * STAGE_BYTES)     // 81920

// Scratch (static device globals: allocation-guard safe)
__device__ __half g_xh[(size_t)MTOK * CDIM];   // x in fp16
__device__ __half g_h [(size_t)MTOK * HDIM];   // hidden (fp16, post-GELU)
__device__ __half g_w1h[(size_t)HDIM * CDIM];  // sign(w1) in fp16
__device__ __half g_w2h[(size_t)CDIM * HDIM];  // sign(w2) in fp16
__device__ float  g_alpha1[HDIM];
__device__ float  g_alpha2[CDIM];

// ---------------------------------------------------------------------------
// helpers
// ---------------------------------------------------------------------------
__device__ __forceinline__ uint32_t smem_u32(const void* p) {
    return (uint32_t)__cvta_generic_to_shared(p);
}
__device__ __forceinline__ void cp_async16(uint32_t dst, const void* src, int src_bytes) {
    asm volatile("cp.async.cg.shared.global [%0], [%1], 16, %2;\n"
                 :: "r"(dst), "l"(src), "r"(src_bytes));
}
__device__ __forceinline__ void cp_commit() {
    asm volatile("cp.async.commit_group;\n" ::: "memory");
}
template <int N>
__device__ __forceinline__ void cp_wait() {
    asm volatile("cp.async.wait_group %0;\n" :: "n"(N) : "memory");
}
__device__ __forceinline__ void ldsm_x4(uint32_t& r0, uint32_t& r1, uint32_t& r2,
                                        uint32_t& r3, uint32_t addr) {
    asm volatile("ldmatrix.sync.aligned.m8n8.x4.shared.b16 {%0,%1,%2,%3}, [%4];\n"
                 : "=r"(r0), "=r"(r1), "=r"(r2), "=r"(r3) : "r"(addr));
}
// fp16 MMA, fp32 accumulate: D[16,8] += A[16,16] * B[16,8]
__device__ __forceinline__ void mma_f16(float c[4], const uint32_t a[4], const uint32_t b[2]) {
    asm volatile(
        "mma.sync.aligned.m16n8k16.row.col.f32.f16.f16.f32 "
        "{%0,%1,%2,%3}, {%4,%5,%6,%7}, {%8,%9}, {%0,%1,%2,%3};\n"
        : "+f"(c[0]), "+f"(c[1]), "+f"(c[2]), "+f"(c[3])
        : "r"(a[0]), "r"(a[1]), "r"(a[2]), "r"(a[3]), "r"(b[0]), "r"(b[1]));
}

// ---------------------------------------------------------------------------
// prep kernels
// ---------------------------------------------------------------------------
__global__ void convert_x_kernel(const float* __restrict__ x, __half* __restrict__ xh, int n4) {
    int i = blockIdx.x * blockDim.x + threadIdx.x;
    if (i < n4) {
        float4 v = ((const float4*)x)[i];
        __half2 h0 = __floats2half2_rn(v.x, v.y);
        __half2 h1 = __floats2half2_rn(v.z, v.w);
        uint2 u;
        u.x = *(uint32_t*)&h0;
        u.y = *(uint32_t*)&h1;
        ((uint2*)xh)[i] = u;
    }
}

__global__ void binarize_h_kernel(const float* __restrict__ w, __half* __restrict__ ws,
                                  float* __restrict__ alpha, int cols) {
    int r = blockIdx.x;
    const float* wr = w + (size_t)r * cols;
    __half* wsr = ws + (size_t)r * cols;
    float s = 0.f;
    for (int c = threadIdx.x; c < cols; c += blockDim.x) {
        float v = wr[c];
        s += fabsf(v);
        wsr[c] = __float2half((v > 0.f) ? 1.f : ((v < 0.f) ? -1.f : 0.f));
    }
    #pragma unroll
    for (int o = 16; o; o >>= 1) s += __shfl_xor_sync(0xffffffffu, s, o);
    __shared__ float red[8];
    if ((threadIdx.x & 31) == 0) red[threadIdx.x >> 5] = s;
    __syncthreads();
    if (threadIdx.x < 8) {
        float v = red[threadIdx.x];
        #pragma unroll
        for (int o = 4; o; o >>= 1) v += __shfl_xor_sync(0xffu, v, o);
        if (threadIdx.x == 0) alpha[r] = v / (float)cols;
    }
}

// ---------------------------------------------------------------------------
// GEMM: C[m,n] = epi( alpha[n] * sum_k A[m,k]*B[n,k] + bias[n] )
// A: [M,K] row-major fp16, B: [N,K] row-major fp16 (values ±1)
// EPI 0: gelu(exact)+clip, store fp16 (feeds GEMM2); EPI 1: affine, store fp32
// ---------------------------------------------------------------------------
template <int EPI>
__global__ void __launch_bounds__(256, 2)
gemm_bin(const __half* __restrict__ A, const __half* __restrict__ B,
         const float* __restrict__ alpha, const float* __restrict__ bias,
         void* __restrict__ outp, int M, int N, int K) {
    extern __shared__ __align__(128) char smem[];
    const uint32_t sb = smem_u32(smem);

    const int tid = threadIdx.x;
    const int lane = tid & 31;
    const int warp = tid >> 5;
    const int wm = warp & 3;   // 4 warps along M (4*32 = 128)
    const int wn = warp >> 2;  // 2 warps along N (2*64 = 128)
    const int m0 = blockIdx.y * BM;
    const int n0 = blockIdx.x * BN;
    const int g = lane >> 2, t = lane & 3;

    // ldmatrix per-lane byte offsets (within stage)
    // A x4: groups: (rows+0,k0) (rows+8,k0) (rows+0,k8) (rows+8,k8)
    const int lr8 = lane & 7;
    const uint32_t a_off = (uint32_t)((wm * 32 + lr8 + ((lane >> 3) & 1) * 8) * RSTRIDE_B
                                      + ((lane >> 4) & 1) * 16);
    // B x4: groups: (rows+0,k0) (rows+0,k8) (rows+8,k0) (rows+8,k8)
    const uint32_t b_off = (uint32_t)(TILE_BYTES
                                      + (wn * 64 + lr8 + ((lane >> 4) & 1) * 8) * RSTRIDE_B
                                      + ((lane >> 3) & 1) * 16);

    float acc[2][8][4];
    #pragma unroll
    for (int i = 0; i < 2; ++i)
        #pragma unroll
        for (int j = 0; j < 8; ++j)
            #pragma unroll
            for (int q = 0; q < 4; ++q) acc[i][j][q] = 0.f;

    const int Ktiles = K / BK;

    auto load_tile = [&](int kt, int s) {
        const size_t kb = (size_t)kt * BK;     // halves
        uint32_t as = sb + (uint32_t)s * STAGE_BYTES;
        uint32_t bs = as + TILE_BYTES;
        #pragma unroll
        for (int p = 0; p < 2; ++p) {
            int idx = p * 256 + tid;     // 0..511
            int row = idx >> 2;          // 0..127
            int seg = idx & 3;           // 0..3 (16B each; row = 64B data)
            int am = m0 + row;
            bool pa = am < M;
            const __half* gpa = A + (size_t)(pa ? am : 0) * K + kb + seg * 8;
            cp_async16(as + row * RSTRIDE_B + seg * 16, gpa, pa ? 16 : 0);
            const __half* gpb = B + (size_t)(n0 + row) * K + kb + seg * 8;
            cp_async16(bs + row * RSTRIDE_B + seg * 16, gpb, 16);
        }
    };

    // prologue
    #pragma unroll
    for (int s = 0; s < NSTAGE - 1; ++s) {
        load_tile(s, s);
        cp_commit();
    }

    for (int kt = 0; kt < Ktiles; ++kt) {
        cp_wait<NSTAGE - 2>();
        __syncthreads();

        int knext = kt + NSTAGE - 1;
        if (knext < Ktiles) load_tile(knext, knext % NSTAGE);
        cp_commit();

        const uint32_t stage = sb + (uint32_t)(kt % NSTAGE) * STAGE_BYTES;

        #pragma unroll
        for (int kk = 0; kk < 2; ++kk) {          // two K=16 chunks per BK=32
            uint32_t af[2][4];
            uint32_t bf[8][2];
            ldsm_x4(af[0][0], af[0][1], af[0][2], af[0][3],
                    stage + a_off + kk * 32);
            ldsm_x4(af[1][0], af[1][1], af[1][2], af[1][3],
                    stage + a_off + 16 * RSTRIDE_B + kk * 32);
            #pragma unroll
            for (int p = 0; p < 4; ++p)
                ldsm_x4(bf[2 * p][0], bf[2 * p][1], bf[2 * p + 1][0], bf[2 * p + 1][1],
                        stage + b_off + p * (16 * RSTRIDE_B) + kk * 32);
            #pragma unroll
            for (int mi = 0; mi < 2; ++mi)
                #pragma unroll
                for (int ni = 0; ni < 8; ++ni)
                    mma_f16(acc[mi][ni], af[mi], bf[ni]);
        }
    }

    // epilogue (accumulator layout identical to validated version)
    #pragma unroll
    for (int ni = 0; ni < 8; ++ni) {
        int col = n0 + wn * 64 + ni * 8 + t * 2;
        float al0 = alpha[col], al1 = alpha[col + 1];
        float bi0 = bias[col], bi1 = bias[col + 1];
        #pragma unroll
        for (int mi = 0; mi < 2; ++mi) {
            int row = m0 + wm * 32 + mi * 16 + g;
            #pragma unroll
            for (int h = 0; h < 2; ++h) { // h=0: rows g, h=1: rows g+8
                int r = row + h * 8;
                if (r < M) {
                    float v0 = al0 * acc[mi][ni][h * 2 + 0] + bi0;
                    float v1 = al1 * acc[mi][ni][h * 2 + 1] + bi1;
                    if (EPI == 0) {
                        v0 = 0.5f * v0 * (1.f + erff(v0 * 0.7071067811865476f));
                        v1 = 0.5f * v1 * (1.f + erff(v1 * 0.7071067811865476f));
                        v0 = fminf(fmaxf(v0, -10.f), 10.f);
                        v1 = fminf(fmaxf(v1, -10.f), 10.f);
                        __half2 hv = __floats2half2_rn(v0, v1);
                        *(__half2*)((__half*)outp + (size_t)r * N + col) = hv;
                    } else {
                        float2 fv = make_float2(v0, v1);
                        *(float2*)((float*)outp + (size_t)r * N + col) = fv;
                    }
                }
            }
        }
    }
}

// ---------------------------------------------------------------------------
extern "C" void kernel_launch(void* const* d_in, const int* in_sizes, int n_in,
                              void* d_out, int out_size) {
    const float* x  = (const float*)d_in[0];
    const float* w1 = (const float*)d_in[1];
    const float* b1 = (const float*)d_in[2];
    const float* w2 = (const float*)d_in[3];
    const float* b2 = (const float*)d_in[4];

    const int M = in_sizes[0] / CDIM;   // 12608
    const int H = in_sizes[2];          // 3072
    const int C = in_sizes[4];          // 768

    __half *xh, *hbuf, *w1h, *w2h;
    float *a1, *a2;
    cudaGetSymbolAddress((void**)&xh,   g_xh);
    cudaGetSymbolAddress((void**)&hbuf, g_h);
    cudaGetSymbolAddress((void**)&w1h,  g_w1h);
    cudaGetSymbolAddress((void**)&w2h,  g_w2h);
    cudaGetSymbolAddress((void**)&a1,   g_alpha1);
    cudaGetSymbolAddress((void**)&a2,   g_alpha2);

    int n4 = (M * C) / 4;
    convert_x_kernel<<<(n4 + 255) / 256, 256>>>(x, xh, n4);
    binarize_h_kernel<<<H, 256>>>(w1, w1h, a1, C);
    binarize_h_kernel<<<C, 256>>>(w2, w2h, a2, H);

    cudaFuncSetAttribute((const void*)gemm_bin<0>,
                         cudaFuncAttributeMaxDynamicSharedMemorySize, SMEM_TOTAL);
    cudaFuncSetAttribute((const void*)gemm_bin<1>,
                         cudaFuncAttributeMaxDynamicSharedMemorySize, SMEM_TOTAL);

    dim3 grid1(H / BN, (M + BM - 1) / BM);   // (24, 99)
    gemm_bin<0><<<grid1, 256, SMEM_TOTAL>>>(xh, w1h, a1, b1, hbuf, M, H, C);

    dim3 grid2(C / BN, (M + BM - 1) / BM);   // (6, 99)
    gemm_bin<1><<<grid2, 256, SMEM_TOTAL>>>(hbuf, w2h, a2, b2, d_out, M, C, H);
}

// round 8
// speedup vs baseline: 2.1362x; 1.0204x over previous
#include <cuda_runtime.h>
#include <cuda_fp16.h>
#include <cstdint>
#include <math.h>

// Problem constants (bi_Mlp: x[64,197,768], H=3072)
#define MTOK 12608
#define CDIM 768
#define HDIM 3072

#define BM 128
#define BN 128
#define BK 32               // halves of K per tile
#define NSTAGE 4
#define NTHREADS 128        // 4 warps, each 64x64
#define RSTRIDE_B 80        // bytes per smem row (64 data + 16 pad) -> conflict-free
#define TILE_BYTES (128 * RSTRIDE_B)          // 10240
#define STAGE_BYTES (2 * TILE_BYTES)          // 20480 (A + B)
#define SMEM_TOTAL (NSTAGE * STAGE_BYTES)     // 81920

// Scratch (static device globals: allocation-guard safe)
__device__ __half g_xh[(size_t)MTOK * CDIM];   // x in fp16
__device__ __half g_h [(size_t)MTOK * HDIM];   // hidden (fp16, post-GELU)
__device__ __half g_w1h[(size_t)HDIM * CDIM];  // sign(w1) in fp16
__device__ __half g_w2h[(size_t)CDIM * HDIM];  // sign(w2) in fp16
__device__ float  g_alpha1[HDIM];
__device__ float  g_alpha2[CDIM];

// ---------------------------------------------------------------------------
// helpers
// ---------------------------------------------------------------------------
__device__ __forceinline__ uint32_t smem_u32(const void* p) {
    return (uint32_t)__cvta_generic_to_shared(p);
}
__device__ __forceinline__ void cp_async16(uint32_t dst, const void* src, int src_bytes) {
    asm volatile("cp.async.cg.shared.global [%0], [%1], 16, %2;\n"
                 :: "r"(dst), "l"(src), "r"(src_bytes));
}
__device__ __forceinline__ void cp_commit() {
    asm volatile("cp.async.commit_group;\n" ::: "memory");
}
template <int N>
__device__ __forceinline__ void cp_wait() {
    asm volatile("cp.async.wait_group %0;\n" :: "n"(N) : "memory");
}
__device__ __forceinline__ void ldsm_x4(uint32_t& r0, uint32_t& r1, uint32_t& r2,
                                        uint32_t& r3, uint32_t addr) {
    asm volatile("ldmatrix.sync.aligned.m8n8.x4.shared.b16 {%0,%1,%2,%3}, [%4];\n"
                 : "=r"(r0), "=r"(r1), "=r"(r2), "=r"(r3) : "r"(addr));
}
// fp16 MMA, fp32 accumulate: D[16,8] += A[16,16] * B[16,8]
__device__ __forceinline__ void mma_f16(float c[4], const uint32_t a[4], const uint32_t b[2]) {
    asm volatile(
        "mma.sync.aligned.m16n8k16.row.col.f32.f16.f16.f32 "
        "{%0,%1,%2,%3}, {%4,%5,%6,%7}, {%8,%9}, {%0,%1,%2,%3};\n"
        : "+f"(c[0]), "+f"(c[1]), "+f"(c[2]), "+f"(c[3])
        : "r"(a[0]), "r"(a[1]), "r"(a[2]), "r"(a[3]), "r"(b[0]), "r"(b[1]));
}

// ---------------------------------------------------------------------------
// prep kernels
// ---------------------------------------------------------------------------
__global__ void convert_x_kernel(const float* __restrict__ x, __half* __restrict__ xh, int n4) {
    int i = blockIdx.x * blockDim.x + threadIdx.x;
    if (i < n4) {
        float4 v = ((const float4*)x)[i];
        __half2 h0 = __floats2half2_rn(v.x, v.y);
        __half2 h1 = __floats2half2_rn(v.z, v.w);
        uint2 u;
        u.x = *(uint32_t*)&h0;
        u.y = *(uint32_t*)&h1;
        ((uint2*)xh)[i] = u;
    }
}

__global__ void binarize_h_kernel(const float* __restrict__ w, __half* __restrict__ ws,
                                  float* __restrict__ alpha, int cols) {
    int r = blockIdx.x;
    const float* wr = w + (size_t)r * cols;
    __half* wsr = ws + (size_t)r * cols;
    float s = 0.f;
    for (int c = threadIdx.x; c < cols; c += blockDim.x) {
        float v = wr[c];
        s += fabsf(v);
        wsr[c] = __float2half((v > 0.f) ? 1.f : ((v < 0.f) ? -1.f : 0.f));
    }
    #pragma unroll
    for (int o = 16; o; o >>= 1) s += __shfl_xor_sync(0xffffffffu, s, o);
    __shared__ float red[8];
    if ((threadIdx.x & 31) == 0) red[threadIdx.x >> 5] = s;
    __syncthreads();
    if (threadIdx.x < 8) {
        float v = red[threadIdx.x];
        #pragma unroll
        for (int o = 4; o; o >>= 1) v += __shfl_xor_sync(0xffu, v, o);
        if (threadIdx.x == 0) alpha[r] = v / (float)cols;
    }
}

// ---------------------------------------------------------------------------
// GEMM: C[m,n] = epi( alpha[n] * sum_k A[m,k]*B[n,k] + bias[n] )
// A: [M,K] row-major fp16, B: [N,K] row-major fp16 (values ±1)
// 4 warps, warp tile 64x64. EPI 0: gelu+clip -> fp16; EPI 1: affine -> fp32
// ---------------------------------------------------------------------------
template <int EPI>
__global__ void __launch_bounds__(NTHREADS, 2)
gemm_bin(const __half* __restrict__ A, const __half* __restrict__ B,
         const float* __restrict__ alpha, const float* __restrict__ bias,
         void* __restrict__ outp, int M, int N, int K) {
    extern __shared__ __align__(128) char smem[];
    const uint32_t sb = smem_u32(smem);

    const int tid = threadIdx.x;
    const int lane = tid & 31;
    const int warp = tid >> 5;
    const int wm = warp & 1;   // 2 warps along M (2*64 = 128)
    const int wn = warp >> 1;  // 2 warps along N (2*64 = 128)
    const int m0 = blockIdx.y * BM;
    const int n0 = blockIdx.x * BN;
    const int g = lane >> 2, t = lane & 3;

    // ldmatrix per-lane byte offsets (within stage)
    const int lr8 = lane & 7;
    // A x4 groups: (rows+0,k0) (rows+8,k0) (rows+0,k8) (rows+8,k8)
    const uint32_t a_off = (uint32_t)((wm * 64 + lr8 + ((lane >> 3) & 1) * 8) * RSTRIDE_B
                                      + ((lane >> 4) & 1) * 16);
    // B x4 groups: (rows+0,k0) (rows+0,k8) (rows+8,k0) (rows+8,k8)
    const uint32_t b_off = (uint32_t)(TILE_BYTES
                                      + (wn * 64 + lr8 + ((lane >> 4) & 1) * 8) * RSTRIDE_B
                                      + ((lane >> 3) & 1) * 16);

    float acc[4][8][4];
    #pragma unroll
    for (int i = 0; i < 4; ++i)
        #pragma unroll
        for (int j = 0; j < 8; ++j)
            #pragma unroll
            for (int q = 0; q < 4; ++q) acc[i][j][q] = 0.f;

    const int Ktiles = K / BK;

    // hoisted cp.async bases: each thread handles rows tid>>2 + 32*p, seg tid&3
    const int ldrow = tid >> 2;          // 0..31
    const int ldseg = tid & 3;           // 0..3
    const __half* aBase[4];
    const __half* bBase[4];
    uint32_t sA[4], sB[4];
    #pragma unroll
    for (int p = 0; p < 4; ++p) {
        int row = ldrow + 32 * p;
        int am = m0 + row;
        aBase[p] = A + (size_t)(am < M ? am : 0) * K + ldseg * 8;
        bBase[p] = B + (size_t)(n0 + row) * K + ldseg * 8;
        sA[p] = sb + row * RSTRIDE_B + ldseg * 16;
        sB[p] = sA[p] + TILE_BYTES;
    }
    const int aPred = (m0 + ldrow + 96) < M ? 16 : ((m0 + ldrow) < M ? -1 : 0);
    // aPred: 16 = all rows valid; 0 = none; -1 = mixed (per-row check)

    auto load_tile = [&](int kt, int s) {
        const uint32_t so = (uint32_t)s * STAGE_BYTES;
        const size_t kb = (size_t)kt * BK;
        #pragma unroll
        for (int p = 0; p < 4; ++p) {
            int bytes = (aPred == 16) ? 16
                       : ((m0 + ldrow + 32 * p) < M ? 16 : 0);
            cp_async16(sA[p] + so, aBase[p] + kb, bytes);
            cp_async16(sB[p] + so, bBase[p] + kb, 16);
        }
    };

    // prologue
    #pragma unroll
    for (int s = 0; s < NSTAGE - 1; ++s) {
        load_tile(s, s);
        cp_commit();
    }

    for (int kt = 0; kt < Ktiles; ++kt) {
        cp_wait<NSTAGE - 2>();
        __syncthreads();

        int knext = kt + NSTAGE - 1;
        if (knext < Ktiles) load_tile(knext, knext % NSTAGE);
        cp_commit();

        const uint32_t stage = sb + (uint32_t)(kt % NSTAGE) * STAGE_BYTES;

        #pragma unroll
        for (int kk = 0; kk < 2; ++kk) {          // two K=16 chunks per BK=32
            uint32_t af[4][4];
            uint32_t bf[8][2];
            #pragma unroll
            for (int mi = 0; mi < 4; ++mi)
                ldsm_x4(af[mi][0], af[mi][1], af[mi][2], af[mi][3],
                        stage + a_off + mi * (16 * RSTRIDE_B) + kk * 32);
            #pragma unroll
            for (int p = 0; p < 4; ++p)
                ldsm_x4(bf[2 * p][0], bf[2 * p][1], bf[2 * p + 1][0], bf[2 * p + 1][1],
                        stage + b_off + p * (16 * RSTRIDE_B) + kk * 32);
            #pragma unroll
            for (int mi = 0; mi < 4; ++mi)
                #pragma unroll
                for (int ni = 0; ni < 8; ++ni)
                    mma_f16(acc[mi][ni], af[mi], bf[ni]);
        }
    }

    // epilogue (validated accumulator mapping; mi extended to 0..3)
    #pragma unroll
    for (int ni = 0; ni < 8; ++ni) {
        int col = n0 + wn * 64 + ni * 8 + t * 2;
        float al0 = alpha[col], al1 = alpha[col + 1];
        float bi0 = bias[col], bi1 = bias[col + 1];
        #pragma unroll
        for (int mi = 0; mi < 4; ++mi) {
            int row = m0 + wm * 64 + mi * 16 + g;
            #pragma unroll
            for (int h = 0; h < 2; ++h) { // h=0: rows g, h=1: rows g+8
                int r = row + h * 8;
                if (r < M) {
                    float v0 = al0 * acc[mi][ni][h * 2 + 0] + bi0;
                    float v1 = al1 * acc[mi][ni][h * 2 + 1] + bi1;
                    if (EPI == 0) {
                        v0 = 0.5f * v0 * (1.f + erff(v0 * 0.7071067811865476f));
                        v1 = 0.5f * v1 * (1.f + erff(v1 * 0.7071067811865476f));
                        v0 = fminf(fmaxf(v0, -10.f), 10.f);
                        v1 = fminf(fmaxf(v1, -10.f), 10.f);
                        __half2 hv = __floats2half2_rn(v0, v1);
                        *(__half2*)((__half*)outp + (size_t)r * N + col) = hv;
                    } else {
                        float2 fv = make_float2(v0, v1);
                        *(float2*)((float*)outp + (size_t)r * N + col) = fv;
                    }
                }
            }
        }
    }
}

// ---------------------------------------------------------------------------
extern "C" void kernel_launch(void* const* d_in, const int* in_sizes, int n_in,
                              void* d_out, int out_size) {
    const float* x  = (const float*)d_in[0];
    const float* w1 = (const float*)d_in[1];
    const float* b1 = (const float*)d_in[2];
    const float* w2 = (const float*)d_in[3];
    const float* b2 = (const float*)d_in[4];

    const int M = in_sizes[0] / CDIM;   // 12608
    const int H = in_sizes[2];          // 3072
    const int C = in_sizes[4];          // 768

    __half *xh, *hbuf, *w1h, *w2h;
    float *a1, *a2;
    cudaGetSymbolAddress((void**)&xh,   g_xh);
    cudaGetSymbolAddress((void**)&hbuf, g_h);
    cudaGetSymbolAddress((void**)&w1h,  g_w1h);
    cudaGetSymbolAddress((void**)&w2h,  g_w2h);
    cudaGetSymbolAddress((void**)&a1,   g_alpha1);
    cudaGetSymbolAddress((void**)&a2,   g_alpha2);

    int n4 = (M * C) / 4;
    convert_x_kernel<<<(n4 + 255) / 256, 256>>>(x, xh, n4);
    binarize_h_kernel<<<H, 256>>>(w1, w1h, a1, C);
    binarize_h_kernel<<<C, 256>>>(w2, w2h, a2, H);

    cudaFuncSetAttribute((const void*)gemm_bin<0>,
                         cudaFuncAttributeMaxDynamicSharedMemorySize, SMEM_TOTAL);
    cudaFuncSetAttribute((const void*)gemm_bin<1>,
                         cudaFuncAttributeMaxDynamicSharedMemorySize, SMEM_TOTAL);

    dim3 grid1(H / BN, (M + BM - 1) / BM);   // (24, 99)
    gemm_bin<0><<<grid1, NTHREADS, SMEM_TOTAL>>>(xh, w1h, a1, b1, hbuf, M, H, C);

    dim3 grid2(C / BN, (M + BM - 1) / BM);   // (6, 99)
    gemm_bin<1><<<grid2, NTHREADS, SMEM_TOTAL>>>(hbuf, w2h, a2, b2, d_out, M, C, H);
}

// round 9
// speedup vs baseline: 2.3151x; 1.0838x over previous
#include <cuda_runtime.h>
#include <cuda_fp16.h>
#include <cstdint>
#include <math.h>

// Problem constants (bi_Mlp: x[64,197,768], H=3072)
#define MTOK 12608
#define CDIM 768
#define HDIM 3072

#define BM 128
#define BN 128
#define BK 64               // halves of K per tile (4 kk-chunks)
#define NSTAGE 3
#define NTHREADS 256        // 8 warps, warp tile 32x64 (validated R7 layout)
#define RSTRIDE_B 144       // bytes per smem row (128 data + 16 pad) -> conflict-free
#define TILE_BYTES (128 * RSTRIDE_B)          // 18432
#define STAGE_BYTES (2 * TILE_BYTES)          // 36864 (A + B)
#define SMEM_TOTAL (NSTAGE * STAGE_BYTES)     // 110592

// Scratch (static device globals: allocation-guard safe)
__device__ __half g_xh[(size_t)MTOK * CDIM];   // x in fp16
__device__ __half g_h [(size_t)MTOK * HDIM];   // hidden (fp16, post-GELU)
__device__ __half g_w1h[(size_t)HDIM * CDIM];  // sign(w1) in fp16
__device__ __half g_w2h[(size_t)CDIM * HDIM];  // sign(w2) in fp16
__device__ float  g_alpha1[HDIM];
__device__ float  g_alpha2[CDIM];

// ---------------------------------------------------------------------------
// helpers
// ---------------------------------------------------------------------------
__device__ __forceinline__ uint32_t smem_u32(const void* p) {
    return (uint32_t)__cvta_generic_to_shared(p);
}
__device__ __forceinline__ void cp_async16(uint32_t dst, const void* src, int src_bytes) {
    asm volatile("cp.async.cg.shared.global [%0], [%1], 16, %2;\n"
                 :: "r"(dst), "l"(src), "r"(src_bytes));
}
__device__ __forceinline__ void cp_commit() {
    asm volatile("cp.async.commit_group;\n" ::: "memory");
}
template <int N>
__device__ __forceinline__ void cp_wait() {
    asm volatile("cp.async.wait_group %0;\n" :: "n"(N) : "memory");
}
__device__ __forceinline__ void ldsm_x4(uint32_t& r0, uint32_t& r1, uint32_t& r2,
                                        uint32_t& r3, uint32_t addr) {
    asm volatile("ldmatrix.sync.aligned.m8n8.x4.shared.b16 {%0,%1,%2,%3}, [%4];\n"
                 : "=r"(r0), "=r"(r1), "=r"(r2), "=r"(r3) : "r"(addr));
}
// fp16 MMA, fp32 accumulate: D[16,8] += A[16,16] * B[16,8]
__device__ __forceinline__ void mma_f16(float c[4], const uint32_t a[4], const uint32_t b[2]) {
    asm volatile(
        "mma.sync.aligned.m16n8k16.row.col.f32.f16.f16.f32 "
        "{%0,%1,%2,%3}, {%4,%5,%6,%7}, {%8,%9}, {%0,%1,%2,%3};\n"
        : "+f"(c[0]), "+f"(c[1]), "+f"(c[2]), "+f"(c[3])
        : "r"(a[0]), "r"(a[1]), "r"(a[2]), "r"(a[3]), "r"(b[0]), "r"(b[1]));
}

// ---------------------------------------------------------------------------
// prep kernels
// ---------------------------------------------------------------------------
__global__ void convert_x_kernel(const float* __restrict__ x, __half* __restrict__ xh, int n4) {
    int i = blockIdx.x * blockDim.x + threadIdx.x;
    if (i < n4) {
        float4 v = ((const float4*)x)[i];
        __half2 h0 = __floats2half2_rn(v.x, v.y);
        __half2 h1 = __floats2half2_rn(v.z, v.w);
        uint2 u;
        u.x = *(uint32_t*)&h0;
        u.y = *(uint32_t*)&h1;
        ((uint2*)xh)[i] = u;
    }
}

__global__ void binarize_h_kernel(const float* __restrict__ w, __half* __restrict__ ws,
                                  float* __restrict__ alpha, int cols) {
    int r = blockIdx.x;
    const float* wr = w + (size_t)r * cols;
    __half* wsr = ws + (size_t)r * cols;
    float s = 0.f;
    for (int c = threadIdx.x; c < cols; c += blockDim.x) {
        float v = wr[c];
        s += fabsf(v);
        wsr[c] = __float2half((v > 0.f) ? 1.f : ((v < 0.f) ? -1.f : 0.f));
    }
    #pragma unroll
    for (int o = 16; o; o >>= 1) s += __shfl_xor_sync(0xffffffffu, s, o);
    __shared__ float red[8];
    if ((threadIdx.x & 31) == 0) red[threadIdx.x >> 5] = s;
    __syncthreads();
    if (threadIdx.x < 8) {
        float v = red[threadIdx.x];
        #pragma unroll
        for (int o = 4; o; o >>= 1) v += __shfl_xor_sync(0xffu, v, o);
        if (threadIdx.x == 0) alpha[r] = v / (float)cols;
    }
}

// ---------------------------------------------------------------------------
// GEMM: C[m,n] = epi( alpha[n] * sum_k A[m,k]*B[n,k] + bias[n] )
// A: [M,K] row-major fp16, B: [N,K] row-major fp16 (values ±1)
// 8 warps (wm 0-3, wn 0-1), warp tile 32x64, BK=64, 3-stage cp.async pipeline.
// EPI 0: gelu(exact)+clip -> fp16 (feeds GEMM2); EPI 1: affine -> fp32
// ---------------------------------------------------------------------------
template <int EPI>
__global__ void __launch_bounds__(NTHREADS, 2)
gemm_bin(const __half* __restrict__ A, const __half* __restrict__ B,
         const float* __restrict__ alpha, const float* __restrict__ bias,
         void* __restrict__ outp, int M, int N, int K) {
    extern __shared__ __align__(128) char smem[];
    const uint32_t sb = smem_u32(smem);

    const int tid = threadIdx.x;
    const int lane = tid & 31;
    const int warp = tid >> 5;
    const int wm = warp & 3;   // 4 warps along M (4*32 = 128)
    const int wn = warp >> 2;  // 2 warps along N (2*64 = 128)
    const int m0 = blockIdx.y * BM;
    const int n0 = blockIdx.x * BN;
    const int g = lane >> 2, t = lane & 3;

    // ldmatrix per-lane byte offsets (within stage) — R6/R7-validated grouping
    const int lr8 = lane & 7;
    // A x4 groups: (rows+0,k0) (rows+8,k0) (rows+0,k8) (rows+8,k8)
    const uint32_t a_off = (uint32_t)((wm * 32 + lr8 + ((lane >> 3) & 1) * 8) * RSTRIDE_B
                                      + ((lane >> 4) & 1) * 16);
    // B x4 groups: (rows+0,k0) (rows+0,k8) (rows+8,k0) (rows+8,k8)
    const uint32_t b_off = (uint32_t)(TILE_BYTES
                                      + (wn * 64 + lr8 + ((lane >> 4) & 1) * 8) * RSTRIDE_B
                                      + ((lane >> 3) & 1) * 16);

    float acc[2][8][4];
    #pragma unroll
    for (int i = 0; i < 2; ++i)
        #pragma unroll
        for (int j = 0; j < 8; ++j)
            #pragma unroll
            for (int q = 0; q < 4; ++q) acc[i][j][q] = 0.f;

    const int Ktiles = K / BK;

    // hoisted cp.async bases: thread covers rows (tid>>3)+32p, seg tid&7 (16B)
    const int tr = tid >> 3;             // 0..31
    const int seg = tid & 7;             // 0..7
    const __half* aB = A + (size_t)0 + seg * 8;
    const __half* bB = B + (size_t)(n0 + tr) * K + seg * 8;
    const uint32_t sBase = sb + tr * RSTRIDE_B + seg * 16;

    auto load_tile = [&](int kt, int s) {
        const uint32_t so = (uint32_t)s * STAGE_BYTES;
        const size_t kb = (size_t)kt * BK;
        #pragma unroll
        for (int p = 0; p < 4; ++p) {
            int row = tr + 32 * p;
            int am = m0 + row;
            bool pa = am < M;
            cp_async16(sBase + so + p * (32 * RSTRIDE_B),
                       aB + (size_t)(pa ? am : 0) * K + kb, pa ? 16 : 0);
            cp_async16(sBase + so + p * (32 * RSTRIDE_B) + TILE_BYTES,
                       bB + (size_t)(32 * p) * K + kb, 16);
        }
    };

    // prologue: stages 0,1
    #pragma unroll
    for (int s = 0; s < NSTAGE - 1; ++s) {
        load_tile(s, s);
        cp_commit();
    }

    int stageIdx = 0;
    for (int kt = 0; kt < Ktiles; ++kt) {
        cp_wait<NSTAGE - 2>();
        __syncthreads();

        int knext = kt + NSTAGE - 1;
        int snext = stageIdx + (NSTAGE - 1);
        if (snext >= NSTAGE) snext -= NSTAGE;
        if (knext < Ktiles) load_tile(knext, snext);
        cp_commit();

        const uint32_t stage = sb + (uint32_t)stageIdx * STAGE_BYTES;
        if (++stageIdx == NSTAGE) stageIdx = 0;

        #pragma unroll
        for (int kk = 0; kk < 4; ++kk) {          // four K=16 chunks per BK=64
            uint32_t af[2][4];
            uint32_t bf[8][2];
            ldsm_x4(af[0][0], af[0][1], af[0][2], af[0][3],
                    stage + a_off + kk * 32);
            ldsm_x4(af[1][0], af[1][1], af[1][2], af[1][3],
                    stage + a_off + 16 * RSTRIDE_B + kk * 32);
            #pragma unroll
            for (int p = 0; p < 4; ++p)
                ldsm_x4(bf[2 * p][0], bf[2 * p][1], bf[2 * p + 1][0], bf[2 * p + 1][1],
                        stage + b_off + p * (16 * RSTRIDE_B) + kk * 32);
            #pragma unroll
            for (int mi = 0; mi < 2; ++mi)
                #pragma unroll
                for (int ni = 0; ni < 8; ++ni)
                    mma_f16(acc[mi][ni], af[mi], bf[ni]);
        }
    }

    // epilogue (accumulator layout identical to validated versions)
    #pragma unroll
    for (int ni = 0; ni < 8; ++ni) {
        int col = n0 + wn * 64 + ni * 8 + t * 2;
        float al0 = alpha[col], al1 = alpha[col + 1];
        float bi0 = bias[col], bi1 = bias[col + 1];
        #pragma unroll
        for (int mi = 0; mi < 2; ++mi) {
            int row = m0 + wm * 32 + mi * 16 + g;
            #pragma unroll
            for (int h = 0; h < 2; ++h) { // h=0: rows g, h=1: rows g+8
                int r = row + h * 8;
                if (r < M) {
                    float v0 = al0 * acc[mi][ni][h * 2 + 0] + bi0;
                    float v1 = al1 * acc[mi][ni][h * 2 + 1] + bi1;
                    if (EPI == 0) {
                        v0 = 0.5f * v0 * (1.f + erff(v0 * 0.7071067811865476f));
                        v1 = 0.5f * v1 * (1.f + erff(v1 * 0.7071067811865476f));
                        v0 = fminf(fmaxf(v0, -10.f), 10.f);
                        v1 = fminf(fmaxf(v1, -10.f), 10.f);
                        __half2 hv = __floats2half2_rn(v0, v1);
                        *(__half2*)((__half*)outp + (size_t)r * N + col) = hv;
                    } else {
                        float2 fv = make_float2(v0, v1);
                        *(float2*)((float*)outp + (size_t)r * N + col) = fv;
                    }
                }
            }
        }
    }
}

// ---------------------------------------------------------------------------
extern "C" void kernel_launch(void* const* d_in, const int* in_sizes, int n_in,
                              void* d_out, int out_size) {
    const float* x  = (const float*)d_in[0];
    const float* w1 = (const float*)d_in[1];
    const float* b1 = (const float*)d_in[2];
    const float* w2 = (const float*)d_in[3];
    const float* b2 = (const float*)d_in[4];

    const int M = in_sizes[0] / CDIM;   // 12608
    const int H = in_sizes[2];          // 3072
    const int C = in_sizes[4];          // 768

    __half *xh, *hbuf, *w1h, *w2h;
    float *a1, *a2;
    cudaGetSymbolAddress((void**)&xh,   g_xh);
    cudaGetSymbolAddress((void**)&hbuf, g_h);
    cudaGetSymbolAddress((void**)&w1h,  g_w1h);
    cudaGetSymbolAddress((void**)&w2h,  g_w2h);
    cudaGetSymbolAddress((void**)&a1,   g_alpha1);
    cudaGetSymbolAddress((void**)&a2,   g_alpha2);

    int n4 = (M * C) / 4;
    convert_x_kernel<<<(n4 + 255) / 256, 256>>>(x, xh, n4);
    binarize_h_kernel<<<H, 256>>>(w1, w1h, a1, C);
    binarize_h_kernel<<<C, 256>>>(w2, w2h, a2, H);

    cudaFuncSetAttribute((const void*)gemm_bin<0>,
                         cudaFuncAttributeMaxDynamicSharedMemorySize, SMEM_TOTAL);
    cudaFuncSetAttribute((const void*)gemm_bin<1>,
                         cudaFuncAttributeMaxDynamicSharedMemorySize, SMEM_TOTAL);

    dim3 grid1(H / BN, (M + BM - 1) / BM);   // (24, 99)
    gemm_bin<0><<<grid1, NTHREADS, SMEM_TOTAL>>>(xh, w1h, a1, b1, hbuf, M, H, C);

    dim3 grid2(C / BN, (M + BM - 1) / BM);   // (6, 99)
    gemm_bin<1><<<grid2, NTHREADS, SMEM_TOTAL>>>(hbuf, w2h, a2, b2, d_out, M, C, H);
}